// round 14
// baseline (speedup 1.0000x reference)
#include <cuda_runtime.h>
#include <cuda_bf16.h>
#include <math.h>
#include <stdint.h>

#define TL 50
#define TD 200
#define KSPAD 216         // A row stride in SMEM (bf16) -> 432B, ldsm conflict-free
#define NBLK 3
#define NTHREADS 512
#define WS 204
#define SSTRIDE 52
#define NEGV (-4294967296.0f)
#define LNEPS 1e-8f
#define KSTEPS 13         // 13 x k16 = 208
#define NTILES 25         // 25 x n8 = 200
#define MATSTRIDE (NTILES * KSTEPS * 32)   // uint4 per weight matrix

// SMEM byte offsets
#define SM_AHI 0
#define SM_ALO 27648                    // 64*216*2
#define SM_SX  55296
#define SM_A   (SM_SX + 40800)          // 96096  : Q f32  / h1-hi bf16 (phase alias)
#define SM_B   (SM_A + 40800)           // 136896 : K f32  / h1-lo bf16 (phase alias)
#define SM_V   (SM_B + 40800)           // 177696 : V f32  / h2 f32 (phase alias)
#define SM_SS  (SM_V + 40800)           // 218496
#define SM_KM  (SM_SS + 10400)          // 228896
#define SM_TOTAL (SM_KM + 256)          // 229152

// Fragment-packed weights: [mat(15)][nt(25)][ks(13)][lane(32)] = {bh0,bh1,bl0,bl1}
__device__ uint4 g_wfrag[15 * MATSTRIDE];

// ---------------- SIMT helpers ----------------
__device__ __forceinline__ float wsum(float v) {
#pragma unroll
    for (int o = 16; o > 0; o >>= 1) v += __shfl_xor_sync(0xffffffffu, v, o);
    return v;
}
__device__ __forceinline__ float wmax(float v) {
#pragma unroll
    for (int o = 16; o > 0; o >>= 1) v = fmaxf(v, __shfl_xor_sync(0xffffffffu, v, o));
    return v;
}
__device__ __forceinline__ void ffma2(uint64_t& acc, uint64_t a, uint64_t b) {
    asm("fma.rn.f32x2 %0, %1, %2, %0;" : "+l"(acc) : "l"(a), "l"(b));
}
__device__ __forceinline__ uint64_t rep2(float x) {
    uint64_t r; asm("mov.b64 %0, {%1, %1};" : "=l"(r) : "f"(x)); return r;
}
__device__ __forceinline__ uint64_t pack2(float lo, float hi) {
    uint64_t r; asm("mov.b64 %0, {%1, %2};" : "=l"(r) : "f"(lo), "f"(hi)); return r;
}
__device__ __forceinline__ void unpack2(uint64_t v, float& lo, float& hi) {
    asm("mov.b64 {%0, %1}, %2;" : "=f"(lo), "=f"(hi) : "l"(v));
}

// ---------------- MMA helpers ----------------
__device__ __forceinline__ void ldsm_x4(uint32_t r[4], uint32_t addr) {
    asm volatile("ldmatrix.sync.aligned.m8n8.x4.shared.b16 {%0,%1,%2,%3}, [%4];"
                 : "=r"(r[0]), "=r"(r[1]), "=r"(r[2]), "=r"(r[3]) : "r"(addr));
}
__device__ __forceinline__ void mma16816(float c[4], const uint32_t a[4],
                                         uint32_t b0, uint32_t b1) {
    asm volatile(
        "mma.sync.aligned.m16n8k16.row.col.f32.bf16.bf16.f32 "
        "{%0,%1,%2,%3}, {%4,%5,%6,%7}, {%8,%9}, {%0,%1,%2,%3};"
        : "+f"(c[0]), "+f"(c[1]), "+f"(c[2]), "+f"(c[3])
        : "r"(a[0]), "r"(a[1]), "r"(a[2]), "r"(a[3]), "r"(b0), "r"(b1));
}
__device__ __forceinline__ uint32_t cvt_bf16x2(float hi, float lo) {
    uint32_t h;
    asm("cvt.rn.satfinite.bf16x2.f32 %0, %1, %2;" : "=r"(h) : "f"(hi), "f"(lo));
    return h;
}
// split two f32 (v0=low elem, v1=high elem) into bf16x2 hi + lo words
__device__ __forceinline__ void split2(float v0, float v1, uint32_t& h, uint32_t& l) {
    h = cvt_bf16x2(v1, v0);
    const float h0 = __uint_as_float(h << 16);
    const float h1 = __uint_as_float(h & 0xffff0000u);
    l = cvt_bf16x2(v1 - h1, v0 - h0);
}

// ---------------- prep kernel: W[k][n] f32 -> fragment-packed bf16 hi/lo ----------------
__global__ void prep_kernel(const float* __restrict__ Wq, const float* __restrict__ Wk,
                            const float* __restrict__ Wv, const float* __restrict__ W1,
                            const float* __restrict__ W2) {
    const int mat = blockIdx.x;       // 0..14
    const int nt = blockIdx.y;        // 0..24
    const int blk = mat / 5, wh = mat % 5;
    const float* W = (wh == 0 ? Wq : wh == 1 ? Wk : wh == 2 ? Wv : wh == 3 ? W1 : W2)
                     + blk * TD * TD;
    const int ks = threadIdx.x >> 5;  // 0..12
    const int lane = threadIdx.x & 31;
    const int gid = lane >> 2, tig = lane & 3;
    const int n = nt * 8 + gid;
    const int k0 = ks * 16 + 2 * tig;

    auto rd = [&](int k) -> float { return (k < TD) ? __ldg(W + k * TD + n) : 0.0f; };
    const float v0 = rd(k0),     v1 = rd(k0 + 1);
    const float v2 = rd(k0 + 8), v3 = rd(k0 + 9);

    uint32_t bh0, bl0, bh1, bl1;
    split2(v0, v1, bh0, bl0);
    split2(v2, v3, bh1, bl1);

    g_wfrag[(size_t)mat * MATSTRIDE + (nt * KSTEPS + ks) * 32 + lane] =
        make_uint4(bh0, bh1, bl0, bl1);
}

// ---------------- one ks step over 4 m-tiles for NM matrices ----------------
template<int NM>
__device__ __forceinline__ void mma_ksblock(
    float (&c)[NM][4][4], const uint4 (&bf)[NM],
    uint32_t ahi, uint32_t alo, int ks)
{
    const uint32_t koff = (uint32_t)(ks * 32);
#pragma unroll
    for (int mt = 0; mt < 4; mt++) {
        uint32_t ah[4], al[4];
        const uint32_t aoff = (uint32_t)(mt * 16 * KSPAD * 2) + koff;
        ldsm_x4(ah, ahi + aoff);
        ldsm_x4(al, alo + aoff);
#pragma unroll
        for (int m = 0; m < NM; m++) {
            mma16816(c[m][mt], ah, bf[m].x, bf[m].y);
            mma16816(c[m][mt], al, bf[m].x, bf[m].y);
            mma16816(c[m][mt], ah, bf[m].z, bf[m].w);
        }
    }
}

// ---------------- one n8-tile GEMM over NM matrices, ping-pong B prefetch ----------------
// BF16OUT: write result as bf16 hi/lo into h1 buffers (SM_A / SM_B) instead of f32.
template<int NM, bool RELU, bool BF16OUT>
__device__ __forceinline__ void do_tile(
    const uint4* __restrict__ fr,       // fb + nt*(KSTEPS*32) + lane
    int nt,
    float* const* dsts, const float* const* biases,
    uint32_t ahi, uint32_t alo,
    char* smem, int gid, int tig)
{
    float c[NM][4][4];
#pragma unroll
    for (int m = 0; m < NM; m++)
#pragma unroll
        for (int mt = 0; mt < 4; mt++)
#pragma unroll
            for (int j = 0; j < 4; j++) c[m][mt][j] = 0.0f;

    uint4 b0[NM], b1[NM];
#pragma unroll
    for (int m = 0; m < NM; m++) b0[m] = __ldg(fr + (size_t)m * MATSTRIDE);

#pragma unroll 1
    for (int ks = 0; ks < KSTEPS - 1; ks += 2) {
#pragma unroll
        for (int m = 0; m < NM; m++)
            b1[m] = __ldg(fr + (size_t)m * MATSTRIDE + (ks + 1) * 32);
        mma_ksblock<NM>(c, b0, ahi, alo, ks);
#pragma unroll
        for (int m = 0; m < NM; m++)
            b0[m] = __ldg(fr + (size_t)m * MATSTRIDE + (ks + 2) * 32);
        mma_ksblock<NM>(c, b1, ahi, alo, ks + 1);
    }
    mma_ksblock<NM>(c, b0, ahi, alo, KSTEPS - 1);

    const int col0 = nt * 8 + 2 * tig;
#pragma unroll
    for (int m = 0; m < NM; m++) {
        const float bx = __ldg(biases[m] + col0);
        const float by = __ldg(biases[m] + col0 + 1);
#pragma unroll
        for (int mt = 0; mt < 4; mt++) {
            const int r0 = mt * 16 + gid;
            if (r0 < TL) {
                float v0 = c[m][mt][0] + bx, v1 = c[m][mt][1] + by;
                if (RELU) { v0 = fmaxf(v0, 0.0f); v1 = fmaxf(v1, 0.0f); }
                if (BF16OUT) {
                    uint32_t h, l;
                    split2(v0, v1, h, l);
                    *(uint32_t*)(smem + SM_A + (r0 * KSPAD + col0) * 2) = h;
                    *(uint32_t*)(smem + SM_B + (r0 * KSPAD + col0) * 2) = l;
                } else {
                    float* dst = dsts[m];
                    dst[r0 * WS + col0] = v0;
                    dst[r0 * WS + col0 + 1] = v1;
                }
            }
            const int r1 = mt * 16 + gid + 8;
            if (r1 < TL) {
                float v2 = c[m][mt][2] + bx, v3 = c[m][mt][3] + by;
                if (RELU) { v2 = fmaxf(v2, 0.0f); v3 = fmaxf(v3, 0.0f); }
                if (BF16OUT) {
                    uint32_t h, l;
                    split2(v2, v3, h, l);
                    *(uint32_t*)(smem + SM_A + (r1 * KSPAD + col0) * 2) = h;
                    *(uint32_t*)(smem + SM_B + (r1 * KSPAD + col0) * 2) = l;
                } else {
                    float* dst = dsts[m];
                    dst[r1 * WS + col0] = v2;
                    dst[r1 * WS + col0 + 1] = v3;
                }
            }
        }
    }
}

// ---------------- main kernel ----------------
__global__ void __launch_bounds__(NTHREADS, 1) encoder_kernel(
    const int* __restrict__ tokens, const float* __restrict__ emb,
    const float* __restrict__ bq, const float* __restrict__ bk,
    const float* __restrict__ bv, const float* __restrict__ b1,
    const float* __restrict__ b2,
    const float* __restrict__ lng, const float* __restrict__ lnb,
    float* __restrict__ out)
{
    extern __shared__ char smem[];
    const uint32_t smem_u32 = (uint32_t)__cvta_generic_to_shared(smem);
    float* sx   = (float*)(smem + SM_SX);
    float* bufA = (float*)(smem + SM_A);
    float* bufB = (float*)(smem + SM_B);
    float* bufV = (float*)(smem + SM_V);
    float* sS   = (float*)(smem + SM_SS);
    float* km   = (float*)(smem + SM_KM);

    const int tid = threadIdx.x;
    const int b = blockIdx.x;
    const int warp = tid >> 5, lane = tid & 31;
    const int gid = lane >> 2, tig = lane & 3;
    // lane-adjusted ldsm bases for x's A buffers
    const uint32_t lsoff = ((uint32_t)((lane & 15) * KSPAD + (lane >> 4) * 8)) * 2u;
    const uint32_t xhi_b = smem_u32 + SM_AHI + lsoff;
    const uint32_t xlo_b = smem_u32 + SM_ALO + lsoff;
    const uint32_t h1hi_b = smem_u32 + SM_A + lsoff;
    const uint32_t h1lo_b = smem_u32 + SM_B + lsoff;

    // Zero x hi/lo A buffers once: pad rows [50,64) and pad cols [200,216) are
    // never touched by the fused incremental splits, and NaN-pattern garbage
    // there would poison mma accumulators (NaN * 0 = NaN).
    {
        uint32_t* az = (uint32_t*)(smem + SM_AHI);
        for (int i = tid; i < (2 * 64 * KSPAD) / 2; i += NTHREADS) az[i] = 0u;
    }
    // Embedding gather: sx = emb[tokens[b]] (stride WS) + fused bf16 hi/lo split
    {
        const int* tok = tokens + b * TL;
        for (int idx = tid; idx < TL * (TD / 4); idx += NTHREADS) {
            const int m = idx / (TD / 4);
            const int c = idx - m * (TD / 4);
            const int t = __ldg(tok + m);
            const float4 v = __ldg((const float4*)emb + (size_t)t * (TD / 4) + c);
            *(float4*)(sx + m * WS + c * 4) = v;
            uint32_t h0, l0, h1, l1;
            split2(v.x, v.y, h0, l0);
            split2(v.z, v.w, h1, l1);
            char* ph = smem + SM_AHI + (m * KSPAD + c * 4) * 2;
            char* pl = smem + SM_ALO + (m * KSPAD + c * 4) * 2;
            *(uint32_t*)ph = h0; *(uint32_t*)(ph + 4) = h1;
            *(uint32_t*)pl = l0; *(uint32_t*)(pl + 4) = l1;
        }
    }
    __syncthreads();

    for (int blk = 0; blk < NBLK; blk++) {
        const int m0 = blk * 5;
        const float* bq_ = bq + blk * TD;
        const float* bk_ = bk + blk * TD;
        const float* bv_ = bv + blk * TD;
        const float* b1_ = b1 + blk * TD;
        const float* b2_ = b2 + blk * TD;
        const float* g_  = lng + blk * TD;
        const float* be_ = lnb + blk * TD;

        // Row masks (reads sx; disjoint from GEMM outputs)
        for (int r = warp; r < TL; r += NTHREADS / 32) {
            float s = 0.0f;
            for (int c = lane; c < TD; c += 32) s += sx[r * WS + c];
            s = wsum(s);
            if (lane == 0) km[r] = (s == 0.0f) ? 1.0f : 0.0f;
        }

        // QKV: one balanced queue of 50 units (25 QK @NM=2 + 25 V @NM=1)
        {
            const uint4* fbq = g_wfrag + (size_t)m0 * MATSTRIDE;
            const uint4* fbv = g_wfrag + (size_t)(m0 + 2) * MATSTRIDE;
            float* dsts2[2] = {bufA, bufB};
            const float* bias2[2] = {bq_, bk_};
            float* dsts1[1] = {bufV};
            const float* bias1[1] = {bv_};
#pragma unroll 1
            for (int u = warp; u < 50; u += 16) {
                if (u < 25)
                    do_tile<2, true, false>(fbq + u * (KSTEPS * 32) + lane, u,
                                            dsts2, bias2, xhi_b, xlo_b, smem, gid, tig);
                else
                    do_tile<1, true, false>(fbv + (u - 25) * (KSTEPS * 32) + lane, u - 25,
                                            dsts1, bias1, xhi_b, xlo_b, smem, gid, tig);
            }
        }
        __syncthreads();

        // scores = (Q @ K^T)*scale with key mask  (SIMT FFMA2)
        if (tid < 500) {
            const int q = tid / 10;
            const int kk0 = (tid % 10) * 5;
            uint64_t acc[5] = {0ull, 0ull, 0ull, 0ull, 0ull};
#pragma unroll 2
            for (int d = 0; d < TD; d += 4) {
                const float4 qa = *(const float4*)(bufA + q * WS + d);
                const uint64_t q01 = pack2(qa.x, qa.y);
                const uint64_t q23 = pack2(qa.z, qa.w);
#pragma unroll
                for (int j = 0; j < 5; j++) {
                    const float4 kv = *(const float4*)(bufB + (kk0 + j) * WS + d);
                    ffma2(acc[j], q01, pack2(kv.x, kv.y));
                    ffma2(acc[j], q23, pack2(kv.z, kv.w));
                }
            }
            const float scale = 0.07071067811865475f;  // 1/sqrt(200)
#pragma unroll
            for (int j = 0; j < 5; j++) {
                float l, h;
                unpack2(acc[j], l, h);
                sS[q * SSTRIDE + kk0 + j] =
                    (km[kk0 + j] != 0.0f) ? NEGV : (l + h) * scale;
            }
        }
        __syncthreads();

        // Softmax rows + query mask
        for (int q = warp; q < TL; q += NTHREADS / 32) {
            const float a  = sS[q * SSTRIDE + lane];
            const float bb = (lane < TL - 32) ? sS[q * SSTRIDE + 32 + lane] : -3.4e38f;
            const float mx = wmax(fmaxf(a, bb));
            const float ea = expf(a - mx);
            const float eb = (lane < TL - 32) ? expf(bb - mx) : 0.0f;
            const float ssum = wsum(ea + eb);
            const float fac = (1.0f - km[q]) / ssum;
            sS[q * SSTRIDE + lane] = ea * fac;
            if (lane < TL - 32) sS[q * SSTRIDE + 32 + lane] = eb * fac;
        }
        __syncthreads();

        // x += attn @ V  (SIMT FFMA2) + fused bf16 hi/lo refresh of updated columns
        if (tid < 500) {
            const int cg = tid % 50, rg = tid / 50;
            const int n0 = cg * 4, mr = rg * 5;
            uint64_t acc[5][2];
#pragma unroll
            for (int i = 0; i < 5; i++) { acc[i][0] = 0ull; acc[i][1] = 0ull; }
#pragma unroll 2
            for (int kk = 0; kk < TL; kk++) {
                const float4 v = *(const float4*)(bufV + kk * WS + n0);
                const uint64_t v01 = pack2(v.x, v.y);
                const uint64_t v23 = pack2(v.z, v.w);
#pragma unroll
                for (int i = 0; i < 5; i++) {
                    const uint64_t a = rep2(sS[(mr + i) * SSTRIDE + kk]);
                    ffma2(acc[i][0], a, v01);
                    ffma2(acc[i][1], a, v23);
                }
            }
#pragma unroll
            for (int i = 0; i < 5; i++) {
                float a0, a1, a2, a3;
                unpack2(acc[i][0], a0, a1);
                unpack2(acc[i][1], a2, a3);
                float* o = sx + (mr + i) * WS + n0;
                const float x0 = o[0] + a0, x1 = o[1] + a1;
                const float x2 = o[2] + a2, x3 = o[3] + a3;
                o[0] = x0; o[1] = x1; o[2] = x2; o[3] = x3;
                uint32_t h0, l0, h1, l1;
                split2(x0, x1, h0, l0);
                split2(x2, x3, h1, l1);
                char* ph = smem + SM_AHI + ((mr + i) * KSPAD + n0) * 2;
                char* pl = smem + SM_ALO + ((mr + i) * KSPAD + n0) * 2;
                *(uint32_t*)ph = h0; *(uint32_t*)(ph + 4) = h1;
                *(uint32_t*)pl = l0; *(uint32_t*)(pl + 4) = l1;
            }
        }
        __syncthreads();

        // FFN1: h1 = relu(x @ W1 + b1) -> bf16 hi/lo directly (overlays dead Q/K f32).
        // Also zero h1 pad cols [200,216) — Q/K f32 writes scribbled them this iter.
        {
            const uint4* fb1 = g_wfrag + (size_t)(m0 + 3) * MATSTRIDE;
            const float* bias1[1] = {b1_};
            // pad zeroing: 64 rows x 8 u32-chunks x 2 buffers = 1024 u32
            for (int i = tid; i < 64 * 8; i += NTHREADS) {
                const int r = i >> 3, c4 = i & 7;   // c4: 8 x u32 = 16 bf16 cols
                *(uint32_t*)(smem + SM_A + (r * KSPAD + 200) * 2 + c4 * 4) = 0u;
                *(uint32_t*)(smem + SM_B + (r * KSPAD + 200) * 2 + c4 * 4) = 0u;
            }
#pragma unroll 1
            for (int nt = warp; nt < NTILES; nt += 16)
                do_tile<1, true, true>(fb1 + nt * (KSTEPS * 32) + lane, nt,
                                       nullptr, bias1, xhi_b, xlo_b, smem, gid, tig);
        }
        __syncthreads();

        // FFN2: h2 = h1 @ W2 + b2 -> f32 into bufV (V dead)
        {
            const uint4* fb2 = g_wfrag + (size_t)(m0 + 4) * MATSTRIDE;
            float* dsts1[1] = {bufV};
            const float* bias1[1] = {b2_};
#pragma unroll 1
            for (int nt = warp; nt < NTILES; nt += 16)
                do_tile<1, false, false>(fb2 + nt * (KSTEPS * 32) + lane, nt,
                                         dsts1, bias1, h1hi_b, h1lo_b, smem, gid, tig);
        }
        __syncthreads();

        // LayerNorm(h2)*g + be, residual into sx, fused bf16 hi/lo refresh
        {
            __nv_bfloat16* xhi = (__nv_bfloat16*)(smem + SM_AHI);
            __nv_bfloat16* xlo = (__nv_bfloat16*)(smem + SM_ALO);
            for (int r = warp; r < TL; r += NTHREADS / 32) {
                float hbuf[7];
                int nc = 0;
                float s = 0.0f;
                for (int c = lane; c < TD; c += 32) {
                    const float h = bufV[r * WS + c];
                    hbuf[nc++] = h;
                    s += h;
                }
                s = wsum(s);
                const float mu = s * (1.0f / TD);
                float v = 0.0f;
                for (int i = 0; i < nc; i++) {
                    const float dd = hbuf[i] - mu;
                    v = fmaf(dd, dd, v);
                }
                v = wsum(v);
                const float inv = rsqrtf(v * (1.0f / TD) + LNEPS);
                nc = 0;
                for (int c = lane; c < TD; c += 32) {
                    const float y = (hbuf[nc++] - mu) * inv * __ldg(g_ + c) + __ldg(be_ + c);
                    const float xv = sx[r * WS + c] + y;
                    sx[r * WS + c] = xv;
                    const __nv_bfloat16 hb = __float2bfloat16(xv);
                    xhi[r * KSPAD + c] = hb;
                    xlo[r * KSPAD + c] = __float2bfloat16(xv - __bfloat162float(hb));
                }
            }
        }
        __syncthreads();
    }

    // Write out (dense 200 stride)
    {
        float4* o = (float4*)(out + (size_t)b * TL * TD);
        for (int idx = tid; idx < TL * (TD / 4); idx += NTHREADS) {
            const int m = idx / (TD / 4);
            const int c = idx - m * (TD / 4);
            o[idx] = *(const float4*)(sx + m * WS + c * 4);
        }
    }
}

extern "C" void kernel_launch(void* const* d_in, const int* in_sizes, int n_in,
                              void* d_out, int out_size) {
    const int*   tokens = (const int*)d_in[0];
    const float* emb = (const float*)d_in[1];
    const float* Wq  = (const float*)d_in[2];
    const float* bq  = (const float*)d_in[3];
    const float* Wk  = (const float*)d_in[4];
    const float* bk  = (const float*)d_in[5];
    const float* Wv  = (const float*)d_in[6];
    const float* bv  = (const float*)d_in[7];
    const float* W1  = (const float*)d_in[8];
    const float* b1  = (const float*)d_in[9];
    const float* W2  = (const float*)d_in[10];
    const float* b2  = (const float*)d_in[11];
    const float* lng = (const float*)d_in[12];
    const float* lnb = (const float*)d_in[13];
    float* out = (float*)d_out;

    const int B = in_sizes[0] / TL;

    dim3 pgrid(15, NTILES, 1);
    prep_kernel<<<pgrid, 13 * 32>>>(Wq, Wk, Wv, W1, W2);

    cudaFuncSetAttribute(encoder_kernel,
                         cudaFuncAttributeMaxDynamicSharedMemorySize, SM_TOTAL);
    encoder_kernel<<<B, NTHREADS, SM_TOTAL>>>(tokens, emb, bq, bk, bv, b1, b2,
                                              lng, lnb, out);
}

// round 15
// speedup vs baseline: 1.2361x; 1.2361x over previous
#include <cuda_runtime.h>
#include <cuda_bf16.h>
#include <math.h>
#include <stdint.h>

#define TL 50
#define TD 200
#define KSPAD 216         // A row stride in SMEM (bf16) -> 432B, ldsm conflict-free
#define NBLK 3
#define NTHREADS 512
#define WS 204
#define SSTRIDE 52
#define NEGV (-4294967296.0f)
#define LNEPS 1e-8f
#define KSTEPS 13         // 13 x k16 = 208
#define NTILES 25         // 25 x n8 = 200
#define SNT 7             // scores n-tiles (keys): 7 x 8 = 56 >= 50
#define MATSTRIDE (NTILES * KSTEPS * 32)   // uint4 per weight matrix

// SMEM byte offsets
#define SM_XHI 0                        // x hi  [64][216] bf16
#define SM_XLO 27648                    // x lo
#define SM_QHI 55296                    // Q hi / h1 hi (phase alias)
#define SM_QLO 82944                    // Q lo / h1 lo
#define SM_KF  110592                   // K frags [7][13][32] uint4 = 46592
#define SM_VF  157184                   // V f32 [50][204] = 40800
#define SM_SS  197984                   // scores [50][52] f32 = 10400
#define SM_KM  208384                   // key masks
#define SM_TOTAL 208640

// Fragment-packed weights: [mat(15)][nt(25)][ks(13)][lane(32)] = {bh0,bh1,bl0,bl1}
__device__ uint4 g_wfrag[15 * MATSTRIDE];

// ---------------- SIMT helpers ----------------
__device__ __forceinline__ float wsum(float v) {
#pragma unroll
    for (int o = 16; o > 0; o >>= 1) v += __shfl_xor_sync(0xffffffffu, v, o);
    return v;
}
__device__ __forceinline__ float wmax(float v) {
#pragma unroll
    for (int o = 16; o > 0; o >>= 1) v = fmaxf(v, __shfl_xor_sync(0xffffffffu, v, o));
    return v;
}
__device__ __forceinline__ void ffma2(uint64_t& acc, uint64_t a, uint64_t b) {
    asm("fma.rn.f32x2 %0, %1, %2, %0;" : "+l"(acc) : "l"(a), "l"(b));
}
__device__ __forceinline__ uint64_t rep2(float x) {
    uint64_t r; asm("mov.b64 %0, {%1, %1};" : "=l"(r) : "f"(x)); return r;
}
__device__ __forceinline__ uint64_t pack2(float lo, float hi) {
    uint64_t r; asm("mov.b64 %0, {%1, %2};" : "=l"(r) : "f"(lo), "f"(hi)); return r;
}
__device__ __forceinline__ void unpack2(uint64_t v, float& lo, float& hi) {
    asm("mov.b64 {%0, %1}, %2;" : "=f"(lo), "=f"(hi) : "l"(v));
}
// bf16x2 word -> two exact f32
__device__ __forceinline__ float bflo(uint32_t w) { return __uint_as_float(w << 16); }
__device__ __forceinline__ float bfhi(uint32_t w) { return __uint_as_float(w & 0xffff0000u); }

// ---------------- MMA helpers ----------------
__device__ __forceinline__ void ldsm_x4(uint32_t r[4], uint32_t addr) {
    asm volatile("ldmatrix.sync.aligned.m8n8.x4.shared.b16 {%0,%1,%2,%3}, [%4];"
                 : "=r"(r[0]), "=r"(r[1]), "=r"(r[2]), "=r"(r[3]) : "r"(addr));
}
__device__ __forceinline__ void mma16816(float c[4], const uint32_t a[4],
                                         uint32_t b0, uint32_t b1) {
    asm volatile(
        "mma.sync.aligned.m16n8k16.row.col.f32.bf16.bf16.f32 "
        "{%0,%1,%2,%3}, {%4,%5,%6,%7}, {%8,%9}, {%0,%1,%2,%3};"
        : "+f"(c[0]), "+f"(c[1]), "+f"(c[2]), "+f"(c[3])
        : "r"(a[0]), "r"(a[1]), "r"(a[2]), "r"(a[3]), "r"(b0), "r"(b1));
}
__device__ __forceinline__ uint32_t cvt_bf16x2(float hi, float lo) {
    uint32_t h;
    asm("cvt.rn.satfinite.bf16x2.f32 %0, %1, %2;" : "=r"(h) : "f"(hi), "f"(lo));
    return h;
}
// split two f32 (v0=low elem, v1=high elem) into bf16x2 hi + lo words
__device__ __forceinline__ void split2(float v0, float v1, uint32_t& h, uint32_t& l) {
    h = cvt_bf16x2(v1, v0);
    const float h0 = __uint_as_float(h << 16);
    const float h1 = __uint_as_float(h & 0xffff0000u);
    l = cvt_bf16x2(v1 - h1, v0 - h0);
}

// ---------------- prep kernel: W[k][n] f32 -> fragment-packed bf16 hi/lo ----------------
__global__ void prep_kernel(const float* __restrict__ Wq, const float* __restrict__ Wk,
                            const float* __restrict__ Wv, const float* __restrict__ W1,
                            const float* __restrict__ W2) {
    const int mat = blockIdx.x;       // 0..14
    const int nt = blockIdx.y;        // 0..24
    const int blk = mat / 5, wh = mat % 5;
    const float* W = (wh == 0 ? Wq : wh == 1 ? Wk : wh == 2 ? Wv : wh == 3 ? W1 : W2)
                     + blk * TD * TD;
    const int ks = threadIdx.x >> 5;  // 0..12
    const int lane = threadIdx.x & 31;
    const int gid = lane >> 2, tig = lane & 3;
    const int n = nt * 8 + gid;
    const int k0 = ks * 16 + 2 * tig;

    auto rd = [&](int k) -> float { return (k < TD) ? __ldg(W + k * TD + n) : 0.0f; };
    const float v0 = rd(k0),     v1 = rd(k0 + 1);
    const float v2 = rd(k0 + 8), v3 = rd(k0 + 9);

    uint32_t bh0, bl0, bh1, bl1;
    split2(v0, v1, bh0, bl0);
    split2(v2, v3, bh1, bl1);

    g_wfrag[(size_t)mat * MATSTRIDE + (nt * KSTEPS + ks) * 32 + lane] =
        make_uint4(bh0, bh1, bl0, bl1);
}

// ---------------- one ks step over 4 m-tiles for NM matrices ----------------
template<int NM>
__device__ __forceinline__ void mma_ksblock(
    float (&c)[NM][4][4], const uint4 (&bf)[NM],
    uint32_t ahi, uint32_t alo, int ks)
{
    const uint32_t koff = (uint32_t)(ks * 32);
#pragma unroll
    for (int mt = 0; mt < 4; mt++) {
        uint32_t ah[4], al[4];
        const uint32_t aoff = (uint32_t)(mt * 16 * KSPAD * 2) + koff;
        ldsm_x4(ah, ahi + aoff);
        ldsm_x4(al, alo + aoff);
#pragma unroll
        for (int m = 0; m < NM; m++) {
            mma16816(c[m][mt], ah, bf[m].x, bf[m].y);
            mma16816(c[m][mt], al, bf[m].x, bf[m].y);
            mma16816(c[m][mt], ah, bf[m].z, bf[m].w);
        }
    }
}

// mainloop with ping-pong B prefetch; accumulators returned in c
template<int NM>
__device__ __forceinline__ void gemm_mainloop(
    float (&c)[NM][4][4], const uint4* __restrict__ fr,
    uint32_t ahi, uint32_t alo)
{
#pragma unroll
    for (int m = 0; m < NM; m++)
#pragma unroll
        for (int mt = 0; mt < 4; mt++)
#pragma unroll
            for (int j = 0; j < 4; j++) c[m][mt][j] = 0.0f;

    uint4 b0[NM], b1[NM];
#pragma unroll
    for (int m = 0; m < NM; m++) b0[m] = __ldg(fr + (size_t)m * MATSTRIDE);

#pragma unroll 1
    for (int ks = 0; ks < KSTEPS - 1; ks += 2) {
#pragma unroll
        for (int m = 0; m < NM; m++)
            b1[m] = __ldg(fr + (size_t)m * MATSTRIDE + (ks + 1) * 32);
        mma_ksblock<NM>(c, b0, ahi, alo, ks);
#pragma unroll
        for (int m = 0; m < NM; m++)
            b0[m] = __ldg(fr + (size_t)m * MATSTRIDE + (ks + 2) * 32);
        mma_ksblock<NM>(c, b1, ahi, alo, ks + 1);
    }
    mma_ksblock<NM>(c, b0, ahi, alo, KSTEPS - 1);
}

// QK fused tile: Q -> bf16 hi/lo A-layout (SM_QHI/SM_QLO); K -> fragment array SM_KF
__device__ __forceinline__ void do_tile_qk(
    const uint4* __restrict__ fr, int nt,
    const float* __restrict__ bq_, const float* __restrict__ bk_,
    uint32_t ahi, uint32_t alo, char* smem, int gid, int tig)
{
    float c[2][4][4];
    gemm_mainloop<2>(c, fr, ahi, alo);

    const int col0 = nt * 8 + 2 * tig;
    const float qbx = __ldg(bq_ + col0), qby = __ldg(bq_ + col0 + 1);
    const float kbx = __ldg(bk_ + col0), kby = __ldg(bk_ + col0 + 1);
    // K fragment slot pieces (depend only on col0)
    const int ks_s = col0 >> 4;
    const int rem = col0 & 15;
    const int tig_s = (rem < 8) ? (rem >> 1) : ((rem - 8) >> 1);
    const int wsel = (rem < 8) ? 0 : 4;
#pragma unroll
    for (int mt = 0; mt < 4; mt++) {
#pragma unroll
        for (int half = 0; half < 2; half++) {
            const int r = mt * 16 + gid + half * 8;
            if (r < TL) {
                // Q
                float q0 = fmaxf(c[0][mt][half * 2 + 0] + qbx, 0.0f);
                float q1 = fmaxf(c[0][mt][half * 2 + 1] + qby, 0.0f);
                uint32_t h, l;
                split2(q0, q1, h, l);
                *(uint32_t*)(smem + SM_QHI + (r * KSPAD + col0) * 2) = h;
                *(uint32_t*)(smem + SM_QLO + (r * KSPAD + col0) * 2) = l;
                // K -> fragment
                float k0 = fmaxf(c[1][mt][half * 2 + 0] + kbx, 0.0f);
                float k1 = fmaxf(c[1][mt][half * 2 + 1] + kby, 0.0f);
                split2(k0, k1, h, l);
                char* p = smem + SM_KF +
                          (((r >> 3) * KSTEPS + ks_s) * 32 + (r & 7) * 4 + tig_s) * 16;
                *(uint32_t*)(p + wsel) = h;
                *(uint32_t*)(p + 8 + wsel) = l;
            }
        }
    }
}

// generic single-matrix tile: BF16OUT -> h1 hi/lo (SM_QHI/SM_QLO), else f32 dst
template<bool RELU, bool BF16OUT>
__device__ __forceinline__ void do_tile_1(
    const uint4* __restrict__ fr, int nt,
    const float* __restrict__ bias, float* __restrict__ dst,
    uint32_t ahi, uint32_t alo, char* smem, int gid, int tig)
{
    float c[1][4][4];
    gemm_mainloop<1>(c, fr, ahi, alo);

    const int col0 = nt * 8 + 2 * tig;
    const float bx = __ldg(bias + col0), by = __ldg(bias + col0 + 1);
#pragma unroll
    for (int mt = 0; mt < 4; mt++) {
#pragma unroll
        for (int half = 0; half < 2; half++) {
            const int r = mt * 16 + gid + half * 8;
            if (r < TL) {
                float v0 = c[0][mt][half * 2 + 0] + bx;
                float v1 = c[0][mt][half * 2 + 1] + by;
                if (RELU) { v0 = fmaxf(v0, 0.0f); v1 = fmaxf(v1, 0.0f); }
                if (BF16OUT) {
                    uint32_t h, l;
                    split2(v0, v1, h, l);
                    *(uint32_t*)(smem + SM_QHI + (r * KSPAD + col0) * 2) = h;
                    *(uint32_t*)(smem + SM_QLO + (r * KSPAD + col0) * 2) = l;
                } else {
                    dst[r * WS + col0] = v0;
                    dst[r * WS + col0 + 1] = v1;
                }
            }
        }
    }
}

// ---------------- main kernel ----------------
__global__ void __launch_bounds__(NTHREADS, 1) encoder_kernel(
    const int* __restrict__ tokens, const float* __restrict__ emb,
    const float* __restrict__ bq, const float* __restrict__ bk,
    const float* __restrict__ bv, const float* __restrict__ b1,
    const float* __restrict__ b2,
    const float* __restrict__ lng, const float* __restrict__ lnb,
    float* __restrict__ out)
{
    extern __shared__ char smem[];
    const uint32_t smem_u32 = (uint32_t)__cvta_generic_to_shared(smem);
    float* vf = (float*)(smem + SM_VF);
    float* sS = (float*)(smem + SM_SS);
    float* km = (float*)(smem + SM_KM);

    const int tid = threadIdx.x;
    const int b = blockIdx.x;
    const int warp = tid >> 5, lane = tid & 31;
    const int gid = lane >> 2, tig = lane & 3;
    const uint32_t lsoff = ((uint32_t)((lane & 15) * KSPAD + (lane >> 4) * 8)) * 2u;
    const uint32_t xhi_b = smem_u32 + SM_XHI + lsoff;
    const uint32_t xlo_b = smem_u32 + SM_XLO + lsoff;
    const uint32_t qhi_b = smem_u32 + SM_QHI + lsoff;
    const uint32_t qlo_b = smem_u32 + SM_QLO + lsoff;

    // Zero all bf16/fragment regions once: pads (x/Q rows>=50, cols>=200; kfrag
    // keys 50..55) are never written afterwards and must be 0 (NaN poisons mma).
    {
        uint32_t* az = (uint32_t*)smem;
        for (int i = tid; i < SM_VF / 4; i += NTHREADS) az[i] = 0u;
    }
    __syncthreads();

    // Embedding gather: x = emb[tokens[b]] stored as bf16 hi/lo only
    {
        const int* tok = tokens + b * TL;
        for (int idx = tid; idx < TL * (TD / 4); idx += NTHREADS) {
            const int m = idx / (TD / 4);
            const int c = idx - m * (TD / 4);
            const int t = __ldg(tok + m);
            const float4 v = __ldg((const float4*)emb + (size_t)t * (TD / 4) + c);
            uint32_t h0, l0, h1, l1;
            split2(v.x, v.y, h0, l0);
            split2(v.z, v.w, h1, l1);
            char* ph = smem + SM_XHI + (m * KSPAD + c * 4) * 2;
            char* pl = smem + SM_XLO + (m * KSPAD + c * 4) * 2;
            *(uint32_t*)ph = h0; *(uint32_t*)(ph + 4) = h1;
            *(uint32_t*)pl = l0; *(uint32_t*)(pl + 4) = l1;
        }
    }
    __syncthreads();

    for (int blk = 0; blk < NBLK; blk++) {
        const int m0 = blk * 5;
        const float* bq_ = bq + blk * TD;
        const float* bk_ = bk + blk * TD;
        const float* bv_ = bv + blk * TD;
        const float* b1_ = b1 + blk * TD;
        const float* b2_ = b2 + blk * TD;
        const float* g_  = lng + blk * TD;
        const float* be_ = lnb + blk * TD;

        // Row masks from reconstructed x (read-only on XHI/XLO; concurrent with QKV)
        {
            const __nv_bfloat16* xhi = (const __nv_bfloat16*)(smem + SM_XHI);
            const __nv_bfloat16* xlo = (const __nv_bfloat16*)(smem + SM_XLO);
            for (int r = warp; r < TL; r += NTHREADS / 32) {
                float s = 0.0f;
                for (int c = lane; c < TD; c += 32)
                    s += __bfloat162float(xhi[r * KSPAD + c]) +
                         __bfloat162float(xlo[r * KSPAD + c]);
                s = wsum(s);
                if (lane == 0) km[r] = (s == 0.0f) ? 1.0f : 0.0f;
            }
        }

        // QKV: balanced queue of 50 units (25 QK fused + 25 V)
        {
            const uint4* fbq = g_wfrag + (size_t)m0 * MATSTRIDE;
            const uint4* fbv = g_wfrag + (size_t)(m0 + 2) * MATSTRIDE;
#pragma unroll 1
            for (int u = warp; u < 50; u += 16) {
                if (u < 25)
                    do_tile_qk(fbq + u * (KSTEPS * 32) + lane, u, bq_, bk_,
                               xhi_b, xlo_b, smem, gid, tig);
                else
                    do_tile_1<true, false>(fbv + (u - 25) * (KSTEPS * 32) + lane, u - 25,
                                           bv_, vf, xhi_b, xlo_b, smem, gid, tig);
            }
        }
        __syncthreads();

        // scores = (Q @ K^T)*scale + key mask, via 3-term bf16 mma
        {
            const float scale = 0.07071067811865475f;  // 1/sqrt(200)
#pragma unroll 1
            for (int u = warp; u < 4 * SNT; u += 16) {
                const int nt = u % SNT, mt = u / SNT;
                float c[4] = {0.0f, 0.0f, 0.0f, 0.0f};
#pragma unroll 1
                for (int ks = 0; ks < KSTEPS; ks++) {
                    uint32_t ah[4], al[4];
                    const uint32_t aoff = (uint32_t)(mt * 16 * KSPAD * 2) + ks * 32;
                    ldsm_x4(ah, qhi_b + aoff);
                    ldsm_x4(al, qlo_b + aoff);
                    const uint4 bf = *(const uint4*)(smem + SM_KF +
                                     ((nt * KSTEPS + ks) * 32 + lane) * 16);
                    mma16816(c, ah, bf.x, bf.y);
                    mma16816(c, al, bf.x, bf.y);
                    mma16816(c, ah, bf.z, bf.w);
                }
                const int key0 = nt * 8 + 2 * tig;
#pragma unroll
                for (int half = 0; half < 2; half++) {
                    const int q = mt * 16 + gid + half * 8;
                    if (q < TL) {
                        if (key0 < TL)
                            sS[q * SSTRIDE + key0] =
                                (km[key0] != 0.0f) ? NEGV : c[half * 2] * scale;
                        if (key0 + 1 < TL)
                            sS[q * SSTRIDE + key0 + 1] =
                                (km[key0 + 1] != 0.0f) ? NEGV : c[half * 2 + 1] * scale;
                    }
                }
            }
        }
        __syncthreads();

        // Softmax rows + query mask
        for (int q = warp; q < TL; q += NTHREADS / 32) {
            const float a  = sS[q * SSTRIDE + lane];
            const float bb = (lane < TL - 32) ? sS[q * SSTRIDE + 32 + lane] : -3.4e38f;
            const float mx = wmax(fmaxf(a, bb));
            const float ea = expf(a - mx);
            const float eb = (lane < TL - 32) ? expf(bb - mx) : 0.0f;
            const float ssum = wsum(ea + eb);
            const float fac = (1.0f - km[q]) / ssum;
            sS[q * SSTRIDE + lane] = ea * fac;
            if (lane < TL - 32) sS[q * SSTRIDE + 32 + lane] = eb * fac;
        }
        __syncthreads();

        // x += attn @ V  (SIMT FFMA2); x lives in XHI/XLO (reconstruct-add-split)
        if (tid < 500) {
            const int cg = tid % 50, rg = tid / 50;
            const int n0 = cg * 4, mr = rg * 5;
            uint64_t acc[5][2];
#pragma unroll
            for (int i = 0; i < 5; i++) { acc[i][0] = 0ull; acc[i][1] = 0ull; }
#pragma unroll 2
            for (int kk = 0; kk < TL; kk++) {
                const float4 v = *(const float4*)(vf + kk * WS + n0);
                const uint64_t v01 = pack2(v.x, v.y);
                const uint64_t v23 = pack2(v.z, v.w);
#pragma unroll
                for (int i = 0; i < 5; i++) {
                    const uint64_t a = rep2(sS[(mr + i) * SSTRIDE + kk]);
                    ffma2(acc[i][0], a, v01);
                    ffma2(acc[i][1], a, v23);
                }
            }
#pragma unroll
            for (int i = 0; i < 5; i++) {
                float a0, a1, a2, a3;
                unpack2(acc[i][0], a0, a1);
                unpack2(acc[i][1], a2, a3);
                char* ph = smem + SM_XHI + ((mr + i) * KSPAD + n0) * 2;
                char* pl = smem + SM_XLO + ((mr + i) * KSPAD + n0) * 2;
                const uint32_t oh0 = *(uint32_t*)ph, oh1 = *(uint32_t*)(ph + 4);
                const uint32_t ol0 = *(uint32_t*)pl, ol1 = *(uint32_t*)(pl + 4);
                const float x0 = bflo(oh0) + bflo(ol0) + a0;
                const float x1 = bfhi(oh0) + bfhi(ol0) + a1;
                const float x2 = bflo(oh1) + bflo(ol1) + a2;
                const float x3 = bfhi(oh1) + bfhi(ol1) + a3;
                uint32_t h0, l0, h1, l1;
                split2(x0, x1, h0, l0);
                split2(x2, x3, h1, l1);
                *(uint32_t*)ph = h0; *(uint32_t*)(ph + 4) = h1;
                *(uint32_t*)pl = l0; *(uint32_t*)(pl + 4) = l1;
            }
        }
        __syncthreads();

        // FFN1: h1 = relu(x @ W1 + b1) -> bf16 hi/lo into Q buffers (Q dead)
        {
            const uint4* fb1 = g_wfrag + (size_t)(m0 + 3) * MATSTRIDE;
#pragma unroll 1
            for (int nt = warp; nt < NTILES; nt += 16)
                do_tile_1<true, true>(fb1 + nt * (KSTEPS * 32) + lane, nt,
                                      b1_, nullptr, xhi_b, xlo_b, smem, gid, tig);
        }
        __syncthreads();

        // FFN2: h2 = h1 @ W2 + b2 -> f32 into vf (V dead)
        {
            const uint4* fb2 = g_wfrag + (size_t)(m0 + 4) * MATSTRIDE;
#pragma unroll 1
            for (int nt = warp; nt < NTILES; nt += 16)
                do_tile_1<false, false>(fb2 + nt * (KSTEPS * 32) + lane, nt,
                                        b2_, vf, qhi_b, qlo_b, smem, gid, tig);
        }
        __syncthreads();

        // LayerNorm(h2)*g + be, residual into x (hi/lo)
        {
            __nv_bfloat16* xhi = (__nv_bfloat16*)(smem + SM_XHI);
            __nv_bfloat16* xlo = (__nv_bfloat16*)(smem + SM_XLO);
            for (int r = warp; r < TL; r += NTHREADS / 32) {
                float hbuf[7];
                int nc = 0;
                float s = 0.0f;
                for (int c = lane; c < TD; c += 32) {
                    const float h = vf[r * WS + c];
                    hbuf[nc++] = h;
                    s += h;
                }
                s = wsum(s);
                const float mu = s * (1.0f / TD);
                float v = 0.0f;
                for (int i = 0; i < nc; i++) {
                    const float dd = hbuf[i] - mu;
                    v = fmaf(dd, dd, v);
                }
                v = wsum(v);
                const float inv = rsqrtf(v * (1.0f / TD) + LNEPS);
                nc = 0;
                for (int c = lane; c < TD; c += 32) {
                    const float y = (hbuf[nc++] - mu) * inv * __ldg(g_ + c) + __ldg(be_ + c);
                    const float xv = __bfloat162float(xhi[r * KSPAD + c]) +
                                     __bfloat162float(xlo[r * KSPAD + c]) + y;
                    const __nv_bfloat16 hb = __float2bfloat16(xv);
                    xhi[r * KSPAD + c] = hb;
                    xlo[r * KSPAD + c] = __float2bfloat16(xv - __bfloat162float(hb));
                }
            }
        }
        __syncthreads();
    }

    // Write out: reconstruct x = hi + lo
    {
        float4* o = (float4*)(out + (size_t)b * TL * TD);
        for (int idx = tid; idx < TL * (TD / 4); idx += NTHREADS) {
            const int m = idx / (TD / 4);
            const int c = idx - m * (TD / 4);
            const char* ph = smem + SM_XHI + (m * KSPAD + c * 4) * 2;
            const char* pl = smem + SM_XLO + (m * KSPAD + c * 4) * 2;
            const uint32_t h0 = *(const uint32_t*)ph, h1 = *(const uint32_t*)(ph + 4);
            const uint32_t l0 = *(const uint32_t*)pl, l1 = *(const uint32_t*)(pl + 4);
            float4 v;
            v.x = bflo(h0) + bflo(l0);
            v.y = bfhi(h0) + bfhi(l0);
            v.z = bflo(h1) + bflo(l1);
            v.w = bfhi(h1) + bfhi(l1);
            o[idx] = v;
        }
    }
}

extern "C" void kernel_launch(void* const* d_in, const int* in_sizes, int n_in,
                              void* d_out, int out_size) {
    const int*   tokens = (const int*)d_in[0];
    const float* emb = (const float*)d_in[1];
    const float* Wq  = (const float*)d_in[2];
    const float* bq  = (const float*)d_in[3];
    const float* Wk  = (const float*)d_in[4];
    const float* bk  = (const float*)d_in[5];
    const float* Wv  = (const float*)d_in[6];
    const float* bv  = (const float*)d_in[7];
    const float* W1  = (const float*)d_in[8];
    const float* b1  = (const float*)d_in[9];
    const float* W2  = (const float*)d_in[10];
    const float* b2  = (const float*)d_in[11];
    const float* lng = (const float*)d_in[12];
    const float* lnb = (const float*)d_in[13];
    float* out = (float*)d_out;

    const int B = in_sizes[0] / TL;

    dim3 pgrid(15, NTILES, 1);
    prep_kernel<<<pgrid, 13 * 32>>>(Wq, Wk, Wv, W1, W2);

    cudaFuncSetAttribute(encoder_kernel,
                         cudaFuncAttributeMaxDynamicSharedMemorySize, SM_TOTAL);
    encoder_kernel<<<B, NTHREADS, SM_TOTAL>>>(tokens, emb, bq, bk, bv, b1, b2,
                                              lng, lnb, out);
}